// round 2
// baseline (speedup 1.0000x reference)
#include <cuda_runtime.h>
#include <math.h>

#define Hn     8
#define Nn     512
#define Dn     64
#define DNn    128
#define DEn    64
#define INNERn 512
#define R      4
#define JT     32
#define NCHUNK (Nn / JT)

typedef unsigned long long ull;

__device__ __forceinline__ ull pk2(float lo, float hi) {
    ull r; asm("mov.b64 %0,{%1,%2};" : "=l"(r) : "f"(lo), "f"(hi)); return r;
}
__device__ __forceinline__ float2 upk2(ull v) {
    float2 r; asm("mov.b64 {%0,%1},%2;" : "=f"(r.x), "=f"(r.y) : "l"(v)); return r;
}
__device__ __forceinline__ void fma2(ull& d, ull a, ull b) {
    asm("fma.rn.f32x2 %0,%1,%2,%3;" : "=l"(d) : "l"(a), "l"(b), "l"(d));
}

// ---------------- scratch ----------------
__device__ float g_q  [Hn * Nn * Dn];
__device__ float g_k  [Hn * Nn * Dn];
__device__ float g_v  [Hn * Nn * Dn];
__device__ float g_qe [Hn * Nn * DEn];
__device__ float g_qbe[Hn * Nn];
__device__ float g_att[Hn * Nn * Dn];
__device__ float g_ew [Hn * Nn * DEn];
__device__ float g_M  [INNERn * DNn];   // M[h*64+c][o] = sum_d We[c,h64+d] Wo[h64+d,o]
__device__ float g_bvec[DNn];           // bo + be @ Wo

// ---------------- kernel 1: QKV projection (+ fused qe, qbe) --------
__global__ void __launch_bounds__(256)
qkv_kernel(const float* __restrict__ nodes,
           const float* __restrict__ Wq, const float* __restrict__ bq,
           const float* __restrict__ Wk, const float* __restrict__ bk,
           const float* __restrict__ Wv, const float* __restrict__ bv,
           const float* __restrict__ We, const float* __restrict__ be)
{
    __shared__ float sN[32][DNn];
    __shared__ float sW[DNn][64];

    const int it = blockIdx.x;
    const int ct = blockIdx.y;
    const int mat = ct >> 3;
    const int h   = ct & 7;
    const int colbase = h * 64;
    const float* W    = (mat == 0) ? Wq : (mat == 1 ? Wk : Wv);
    const float* bias = (mat == 0) ? bq : (mat == 1 ? bk : bv);
    float* out        = (mat == 0) ? g_q : (mat == 1 ? g_k : g_v);

    const int i0 = it * 32;
    const int t  = threadIdx.x;

    {
        const float4* nf = (const float4*)(nodes + (size_t)i0 * DNn);
        float4* sNf = (float4*)&sN[0][0];
        #pragma unroll
        for (int r = 0; r < 4; r++) sNf[t + 256 * r] = nf[t + 256 * r];
    }
    #pragma unroll
    for (int r = 0; r < 8; r++) {
        int idx = t + 256 * r;
        int f = idx >> 4, c4 = idx & 15;
        ((float4*)&sW[f][0])[c4] = *(const float4*)(W + (size_t)f * INNERn + colbase + c4 * 4);
    }
    __syncthreads();

    const int col   = t & 63;
    const int ibase = t >> 6;
    float acc[8];
    #pragma unroll
    for (int r = 0; r < 8; r++) acc[r] = 0.f;

    for (int f = 0; f < DNn; f++) {
        float w = sW[f][col];
        #pragma unroll
        for (int r = 0; r < 8; r++) acc[r] += sN[ibase + 4 * r][f] * w;
    }

    const float b  = bias[colbase + col];
    const float sc = (mat == 0) ? 0.125f : 1.0f;
    float vals[8];
    #pragma unroll
    for (int r = 0; r < 8; r++) {
        vals[r] = (acc[r] + b) * sc;
        int i = i0 + ibase + 4 * r;
        out[(size_t)h * (Nn * Dn) + (size_t)i * Dn + col] = vals[r];
    }

    if (mat == 0) {
        float (*sOut)[Dn] = (float(*)[Dn])&sW[0][0];
        __syncthreads();
        #pragma unroll
        for (int r = 0; r < 8; r++) sOut[ibase + 4 * r][col] = vals[r];
        __syncthreads();

        float wreg[Dn];
        #pragma unroll
        for (int d = 0; d < Dn; d++) wreg[d] = We[(size_t)col * INNERn + colbase + d];
        #pragma unroll
        for (int r = 0; r < 8; r++) {
            int i = i0 + ibase + 4 * r;
            float s = 0.f;
            #pragma unroll
            for (int d = 0; d < Dn; d++) s += wreg[d] * sOut[ibase + 4 * r][d];
            g_qe[(size_t)h * (Nn * DEn) + (size_t)i * DEn + col] = s;
        }
        if (col == 0) {
            #pragma unroll
            for (int r = 0; r < 8; r++) {
                int i = i0 + ibase + 4 * r;
                float sb = 0.f;
                for (int d = 0; d < Dn; d++) sb += sOut[ibase + 4 * r][d] * be[colbase + d];
                g_qbe[h * Nn + i] = sb;
            }
        }
    }
}

// ---------------- kernel 2: combined weight precompute + bvec ----------------
__global__ void __launch_bounds__(256)
wcomb_kernel(const float* __restrict__ We, const float* __restrict__ be,
             const float* __restrict__ Wo, const float* __restrict__ bo)
{
    const int b = blockIdx.x;
    const int t = threadIdx.x;
    if (b < 64) {
        const int h  = b >> 3;
        const int c0 = (b & 7) * 8 + (t >> 7) * 4;   // 4 c's per thread
        const int o  = t & 127;
        float acc[4] = {0.f, 0.f, 0.f, 0.f};
        for (int d = 0; d < 64; d++) {
            float wo = Wo[(size_t)(h * 64 + d) * DNn + o];
            #pragma unroll
            for (int cc = 0; cc < 4; cc++)
                acc[cc] += We[(size_t)(c0 + cc) * INNERn + h * 64 + d] * wo;
        }
        #pragma unroll
        for (int cc = 0; cc < 4; cc++)
            g_M[(size_t)(h * 64 + c0 + cc) * DNn + o] = acc[cc];
    } else {
        if (t < 128) {
            float acc = bo[t];
            for (int k = 0; k < INNERn; k++) acc += be[k] * Wo[(size_t)k * DNn + t];
            g_bvec[t] = acc;
        }
    }
}

// ---------------- kernel 3: fused attention (two-pass, full softmax) ----------------
// block: R=4 i-rows, all 8 heads, 256 threads, warp w == head w.
// dynamic smem: sim[8][4][512] + sQ[8][4][64] + sQE[8][4][64] + sQBE[32] + sInv[32]
#define ATTN_SMEM ((16384 + 2048 + 2048 + 32 + 32) * 4)

__global__ void __launch_bounds__(256, 1)
attn2_kernel(const float* __restrict__ edges,
             const float* __restrict__ kmat,
             const float* __restrict__ vmat)
{
    extern __shared__ float smem[];
    float* sim  = smem;            // [h][ii][j]  (h*2048 + ii*512 + j)
    float* sQ   = smem + 16384;    // [h][ii][d]
    float* sQE  = sQ + 2048;
    float* sQBE = sQE + 2048;      // [h*4+ii]
    float* sInv = sQBE + 32;

    const int t = threadIdx.x;
    const int w = t >> 5, l = t & 31;
    const int i0 = blockIdx.x * R;

    // load q / qe / qbe
    {
        const int hi = t >> 3, part = t & 7;   // 32 (h,ii) pairs x 8 threads
        const int h = hi >> 2, ii = hi & 3;
        const float4* qsrc  = (const float4*)(g_q  + (size_t)h * (Nn * Dn)  + (size_t)(i0 + ii) * Dn  + part * 8);
        const float4* qesrc = (const float4*)(g_qe + (size_t)h * (Nn * DEn) + (size_t)(i0 + ii) * DEn + part * 8);
        float4* qd  = (float4*)(sQ  + hi * 64 + part * 8);
        float4* qed = (float4*)(sQE + hi * 64 + part * 8);
        qd[0]  = qsrc[0];  qd[1]  = qsrc[1];
        qed[0] = qesrc[0]; qed[1] = qesrc[1];
        if (t < 32) sQBE[t] = g_qbe[(t >> 2) * Nn + i0 + (t & 3)];
    }
    __syncthreads();

    // ---- Stage A: qk -> sim  (warp = head, lane = j within chunk)
    {
        const float* kb = kmat + (size_t)w * (Nn * Dn);
        for (int jc = 0; jc < 16; jc++) {
            const int j = jc * 32 + l;
            ulonglong2 kr[16];
            const ulonglong2* kp = (const ulonglong2*)(kb + (size_t)j * Dn);
            #pragma unroll
            for (int q = 0; q < 16; q++) kr[q] = kp[q];
            #pragma unroll
            for (int ii = 0; ii < R; ii++) {
                const ulonglong2* qp = (const ulonglong2*)(sQ + w * 256 + ii * 64);
                ull a0 = 0ull, a1 = 0ull;
                #pragma unroll
                for (int q = 0; q < 16; q++) {
                    ulonglong2 qv = qp[q];
                    fma2(a0, qv.x, kr[q].x);
                    fma2(a1, qv.y, kr[q].y);
                }
                float2 f0 = upk2(a0), f1 = upk2(a1);
                sim[w * 2048 + ii * 512 + j] = f0.x + f0.y + f1.x + f1.y + sQBE[w * 4 + ii];
            }
        }
    }
    __syncthreads();

    // ---- Stage B: += qe . edges  (cooperative: pair of lanes per (ii,j))
    {
        const int pair = t >> 1, ii2 = pair >> 5, j2 = pair & 31, half = t & 1;
        for (int chunk = 0; chunk < NCHUNK; chunk++) {
            const int j0 = chunk * JT;
            const ulonglong2* ev = (const ulonglong2*)(edges + ((size_t)(i0 + ii2) * Nn + j0 + j2) * DEn + half * 32);
            ulonglong2 er[8];
            #pragma unroll
            for (int q = 0; q < 8; q++) er[q] = ev[q];
            float sh[Hn];
            #pragma unroll
            for (int h = 0; h < Hn; h++) {
                const ulonglong2* qe = (const ulonglong2*)(sQE + h * 256 + ii2 * 64 + half * 32);
                ull a0 = 0ull, a1 = 0ull;
                #pragma unroll
                for (int q = 0; q < 8; q++) {
                    ulonglong2 qv = qe[q];
                    fma2(a0, qv.x, er[q].x);
                    fma2(a1, qv.y, er[q].y);
                }
                float2 f0 = upk2(a0), f1 = upk2(a1);
                sh[h] = f0.x + f0.y + f1.x + f1.y;
            }
            #pragma unroll
            for (int h = 0; h < Hn; h++) sh[h] += __shfl_xor_sync(0xffffffffu, sh[h], 1);
            if (half == 0) {
                #pragma unroll
                for (int h = 0; h < Hn; h++) sim[h * 2048 + ii2 * 512 + j0 + j2] += sh[h];
            }
        }
    }
    __syncthreads();

    // ---- Stage C: full softmax per row (warp w handles head w)
    {
        #pragma unroll
        for (int ii = 0; ii < R; ii++) {
            float vals[16];
            float mx = -1e30f;
            #pragma unroll
            for (int jc = 0; jc < 16; jc++) {
                vals[jc] = sim[w * 2048 + ii * 512 + jc * 32 + l];
                mx = fmaxf(mx, vals[jc]);
            }
            #pragma unroll
            for (int off = 16; off > 0; off >>= 1) mx = fmaxf(mx, __shfl_xor_sync(0xffffffffu, mx, off));
            float s = 0.f;
            #pragma unroll
            for (int jc = 0; jc < 16; jc++) {
                float e = __expf(vals[jc] - mx);
                s += e;
                sim[w * 2048 + ii * 512 + jc * 32 + l] = e;
            }
            #pragma unroll
            for (int off = 16; off > 0; off >>= 1) s += __shfl_xor_sync(0xffffffffu, s, off);
            if (l == 0) sInv[w * 4 + ii] = 1.0f / s;
        }
    }
    __syncthreads();

    // ---- Stage D: p @ v  (warp = head, lane owns 2 dims)
    {
        const float* vb = vmat + (size_t)w * (Nn * Dn) + 2 * l;
        float a0[R], a1[R];
        #pragma unroll
        for (int ii = 0; ii < R; ii++) { a0[ii] = 0.f; a1[ii] = 0.f; }
        for (int jb = 0; jb < Nn / 4; jb++) {
            float2 vv[4];
            #pragma unroll
            for (int u = 0; u < 4; u++) vv[u] = *(const float2*)(vb + (size_t)(jb * 4 + u) * Dn);
            #pragma unroll
            for (int ii = 0; ii < R; ii++) {
                float4 p4 = *(const float4*)(sim + w * 2048 + ii * 512 + jb * 4);
                a0[ii] += p4.x * vv[0].x + p4.y * vv[1].x + p4.z * vv[2].x + p4.w * vv[3].x;
                a1[ii] += p4.x * vv[0].y + p4.y * vv[1].y + p4.z * vv[2].y + p4.w * vv[3].y;
            }
        }
        #pragma unroll
        for (int ii = 0; ii < R; ii++) {
            float inv = sInv[w * 4 + ii];
            float2 o = make_float2(a0[ii] * inv, a1[ii] * inv);
            *(float2*)(g_att + (size_t)w * (Nn * Dn) + (size_t)(i0 + ii) * Dn + 2 * l) = o;
        }
    }

    // ---- Stage E: ew = p @ edges  (cooperative: (ii, c) per thread)
    {
        const int ii4 = t >> 6, c4 = t & 63;
        ull acc[Hn];
        #pragma unroll
        for (int h = 0; h < Hn; h++) acc[h] = 0ull;
        for (int chunk = 0; chunk < NCHUNK; chunk++) {
            const int j0 = chunk * JT;
            const float* eb = edges + ((size_t)(i0 + ii4) * Nn + j0) * DEn + c4;
            float er[JT];
            #pragma unroll
            for (int j = 0; j < JT; j++) er[j] = eb[(size_t)j * DEn];
            ull e2[16];
            #pragma unroll
            for (int u = 0; u < 16; u++) e2[u] = pk2(er[2 * u], er[2 * u + 1]);
            #pragma unroll
            for (int h = 0; h < Hn; h++) {
                const ulonglong2* pp = (const ulonglong2*)(sim + h * 2048 + ii4 * 512 + j0);
                #pragma unroll
                for (int u = 0; u < 8; u++) {
                    ulonglong2 pv = pp[u];
                    fma2(acc[h], pv.x, e2[2 * u]);
                    fma2(acc[h], pv.y, e2[2 * u + 1]);
                }
            }
        }
        #pragma unroll
        for (int h = 0; h < Hn; h++) {
            float2 f = upk2(acc[h]);
            g_ew[(size_t)h * (Nn * DEn) + (size_t)(i0 + ii4) * DEn + c4] = (f.x + f.y) * sInv[h * 4 + ii4];
        }
    }
}

// ---------------- kernel 4: out = [att|ew] @ [Wo;M] + bvec ----------------
// grid 32, block 256, 16 rows/block, dynamic smem 64KB
#define FUSE_SMEM (16 * 1024 * 4)

__global__ void __launch_bounds__(256)
fuse_out_kernel(const float* __restrict__ Wo, float* __restrict__ out)
{
    extern __shared__ float sA[];     // [16][1024]
    const int t = threadIdx.x;
    const int i0 = blockIdx.x * 16;

    #pragma unroll
    for (int u = 0; u < 16; u++) {
        int idx = t + 256 * u;        // over 4096 float4
        int r = idx >> 8, seg = idx & 255;
        float4 val;
        if (seg < 128) {
            int h = seg >> 4, d4 = seg & 15;
            val = *(const float4*)(g_att + (size_t)h * (Nn * Dn) + (size_t)(i0 + r) * Dn + d4 * 4);
        } else {
            int s2 = seg - 128;
            int h = s2 >> 4, c4 = s2 & 15;
            val = *(const float4*)(g_ew + (size_t)h * (Nn * DEn) + (size_t)(i0 + r) * DEn + c4 * 4);
        }
        *(float4*)(sA + r * 1024 + seg * 4) = val;
    }
    __syncthreads();

    const int row  = t >> 5;          // 0..7 -> rows {row, row+8}
    const int col4 = (t & 31) * 4;
    float4 acc0 = make_float4(0, 0, 0, 0);
    float4 acc1 = make_float4(0, 0, 0, 0);

    const float* a0p = sA + row * 1024;
    const float* a1p = sA + (row + 8) * 1024;

    #pragma unroll 4
    for (int k = 0; k < 512; k++) {
        float4 wv = *(const float4*)(Wo + (size_t)k * DNn + col4);
        float a0 = a0p[k], a1 = a1p[k];
        acc0.x += a0 * wv.x; acc0.y += a0 * wv.y; acc0.z += a0 * wv.z; acc0.w += a0 * wv.w;
        acc1.x += a1 * wv.x; acc1.y += a1 * wv.y; acc1.z += a1 * wv.z; acc1.w += a1 * wv.w;
    }
    #pragma unroll 4
    for (int k = 0; k < 512; k++) {
        float4 wv = *(const float4*)(g_M + (size_t)k * DNn + col4);
        float a0 = a0p[512 + k], a1 = a1p[512 + k];
        acc0.x += a0 * wv.x; acc0.y += a0 * wv.y; acc0.z += a0 * wv.z; acc0.w += a0 * wv.w;
        acc1.x += a1 * wv.x; acc1.y += a1 * wv.y; acc1.z += a1 * wv.z; acc1.w += a1 * wv.w;
    }

    float4 bv = *(const float4*)(g_bvec + col4);
    acc0.x += bv.x; acc0.y += bv.y; acc0.z += bv.z; acc0.w += bv.w;
    acc1.x += bv.x; acc1.y += bv.y; acc1.z += bv.z; acc1.w += bv.w;
    *(float4*)(out + (size_t)(i0 + row) * DNn + col4)     = acc0;
    *(float4*)(out + (size_t)(i0 + row + 8) * DNn + col4) = acc1;
}

// ---------------- launch ----------------
extern "C" void kernel_launch(void* const* d_in, const int* in_sizes, int n_in,
                              void* d_out, int out_size)
{
    const float* nodes = (const float*)d_in[0];
    const float* edges = (const float*)d_in[1];
    const float* Wq = (const float*)d_in[3];
    const float* bq = (const float*)d_in[4];
    const float* Wk = (const float*)d_in[5];
    const float* bk = (const float*)d_in[6];
    const float* Wv = (const float*)d_in[7];
    const float* bv = (const float*)d_in[8];
    const float* We = (const float*)d_in[9];
    const float* be = (const float*)d_in[10];
    const float* Wo = (const float*)d_in[11];
    const float* bo = (const float*)d_in[12];
    float* out = (float*)d_out;

    float* kptr; float* vptr;
    cudaGetSymbolAddress((void**)&kptr, g_k);
    cudaGetSymbolAddress((void**)&vptr, g_v);

    cudaFuncSetAttribute(attn2_kernel, cudaFuncAttributeMaxDynamicSharedMemorySize, ATTN_SMEM);
    cudaFuncSetAttribute(fuse_out_kernel, cudaFuncAttributeMaxDynamicSharedMemorySize, FUSE_SMEM);

    dim3 g1(16, 24);
    qkv_kernel<<<g1, 256>>>(nodes, Wq, bq, Wk, bk, Wv, bv, We, be);
    wcomb_kernel<<<65, 256>>>(We, be, Wo, bo);
    attn2_kernel<<<Nn / R, 256, ATTN_SMEM>>>(edges, kptr, vptr);
    fuse_out_kernel<<<Nn / 16, 256, FUSE_SMEM>>>(Wo, out);
}

// round 3
// speedup vs baseline: 1.1142x; 1.1142x over previous
#include <cuda_runtime.h>
#include <math.h>

#define Hn     8
#define Nn     512
#define Dn     64
#define DNn    128
#define DEn    64
#define INNERn 512

typedef unsigned long long ull;

__device__ __forceinline__ ull pk2(float lo, float hi) {
    ull r; asm("mov.b64 %0,{%1,%2};" : "=l"(r) : "f"(lo), "f"(hi)); return r;
}
__device__ __forceinline__ float2 upk2(ull v) {
    float2 r; asm("mov.b64 {%0,%1},%2;" : "=f"(r.x), "=f"(r.y) : "l"(v)); return r;
}
__device__ __forceinline__ void fma2(ull& d, ull a, ull b) {
    asm("fma.rn.f32x2 %0,%1,%2,%3;" : "=l"(d) : "l"(a), "l"(b), "l"(d));
}

// ---------------- scratch ----------------
__device__ float g_q  [Hn * Nn * Dn];
__device__ float g_k  [Hn * Nn * Dn];
__device__ float g_v  [Hn * Nn * Dn];
__device__ float g_qe [Hn * Nn * DEn];
__device__ float g_qbe[Hn * Nn];
__device__ float g_sim[Hn * Nn * Nn];    // 8 MB: logits -> p (unnormalized)
__device__ float g_sinv[Hn * Nn];        // 1/rowsum
__device__ float g_att[Hn * Nn * Dn];
__device__ float g_ew [Hn * Nn * DEn];
__device__ float g_M  [INNERn * DNn];
__device__ float g_bvec[DNn];

// ---------------- kernel 1: QKV projection (+ fused qe, qbe) --------
__global__ void __launch_bounds__(256)
qkv_kernel(const float* __restrict__ nodes,
           const float* __restrict__ Wq, const float* __restrict__ bq,
           const float* __restrict__ Wk, const float* __restrict__ bk,
           const float* __restrict__ Wv, const float* __restrict__ bv,
           const float* __restrict__ We, const float* __restrict__ be)
{
    __shared__ float sN[32][DNn];
    __shared__ float sW[DNn][64];

    const int it = blockIdx.x;
    const int ct = blockIdx.y;
    const int mat = ct >> 3;
    const int h   = ct & 7;
    const int colbase = h * 64;
    const float* W    = (mat == 0) ? Wq : (mat == 1 ? Wk : Wv);
    const float* bias = (mat == 0) ? bq : (mat == 1 ? bk : bv);
    float* out        = (mat == 0) ? g_q : (mat == 1 ? g_k : g_v);

    const int i0 = it * 32;
    const int t  = threadIdx.x;

    {
        const float4* nf = (const float4*)(nodes + (size_t)i0 * DNn);
        float4* sNf = (float4*)&sN[0][0];
        #pragma unroll
        for (int r = 0; r < 4; r++) sNf[t + 256 * r] = nf[t + 256 * r];
    }
    #pragma unroll
    for (int r = 0; r < 8; r++) {
        int idx = t + 256 * r;
        int f = idx >> 4, c4 = idx & 15;
        ((float4*)&sW[f][0])[c4] = *(const float4*)(W + (size_t)f * INNERn + colbase + c4 * 4);
    }
    __syncthreads();

    const int col   = t & 63;
    const int ibase = t >> 6;
    float acc[8];
    #pragma unroll
    for (int r = 0; r < 8; r++) acc[r] = 0.f;

    for (int f = 0; f < DNn; f++) {
        float w = sW[f][col];
        #pragma unroll
        for (int r = 0; r < 8; r++) acc[r] += sN[ibase + 4 * r][f] * w;
    }

    const float b  = bias[colbase + col];
    const float sc = (mat == 0) ? 0.125f : 1.0f;
    float vals[8];
    #pragma unroll
    for (int r = 0; r < 8; r++) {
        vals[r] = (acc[r] + b) * sc;
        int i = i0 + ibase + 4 * r;
        out[(size_t)h * (Nn * Dn) + (size_t)i * Dn + col] = vals[r];
    }

    if (mat == 0) {
        float (*sOut)[Dn] = (float(*)[Dn])&sW[0][0];
        __syncthreads();
        #pragma unroll
        for (int r = 0; r < 8; r++) sOut[ibase + 4 * r][col] = vals[r];
        __syncthreads();

        float wreg[Dn];
        #pragma unroll
        for (int d = 0; d < Dn; d++) wreg[d] = We[(size_t)col * INNERn + colbase + d];
        #pragma unroll
        for (int r = 0; r < 8; r++) {
            int i = i0 + ibase + 4 * r;
            float s = 0.f;
            #pragma unroll
            for (int d = 0; d < Dn; d++) s += wreg[d] * sOut[ibase + 4 * r][d];
            g_qe[(size_t)h * (Nn * DEn) + (size_t)i * DEn + col] = s;
        }
        if (col == 0) {
            #pragma unroll
            for (int r = 0; r < 8; r++) {
                int i = i0 + ibase + 4 * r;
                float sb = 0.f;
                for (int d = 0; d < Dn; d++) sb += sOut[ibase + 4 * r][d] * be[colbase + d];
                g_qbe[h * Nn + i] = sb;
            }
        }
    }
}

// ---------------- kernel 2: combined weight precompute + bvec ----------------
__global__ void __launch_bounds__(256)
wcomb_kernel(const float* __restrict__ We, const float* __restrict__ be,
             const float* __restrict__ Wo, const float* __restrict__ bo)
{
    const int b = blockIdx.x;
    const int t = threadIdx.x;
    if (b < 64) {
        const int h  = b >> 3;
        const int c0 = (b & 7) * 8 + (t >> 7) * 4;
        const int o  = t & 127;
        float acc[4] = {0.f, 0.f, 0.f, 0.f};
        for (int d = 0; d < 64; d++) {
            float wo = Wo[(size_t)(h * 64 + d) * DNn + o];
            #pragma unroll
            for (int cc = 0; cc < 4; cc++)
                acc[cc] += We[(size_t)(c0 + cc) * INNERn + h * 64 + d] * wo;
        }
        #pragma unroll
        for (int cc = 0; cc < 4; cc++)
            g_M[(size_t)(h * 64 + c0 + cc) * DNn + o] = acc[cc];
    } else {
        if (t < 128) {
            float acc = bo[t];
            for (int k = 0; k < INNERn; k++) acc += be[k] * Wo[(size_t)k * DNn + t];
            g_bvec[t] = acc;
        }
    }
}

// ---------------- kernel 3: sim = q @ k^T + qbe  (register-tiled GEMM) ----------------
// grid (16 itiles, 4 jtiles, 8 heads) = 512 blocks, 256 threads
__global__ void __launch_bounds__(256)
qksim_kernel(const float* __restrict__ kmat)
{
    __shared__ float sQT[64][36];    // [d][i]
    __shared__ float sKT[64][132];   // [d][j]

    const int i0 = blockIdx.x * 32;
    const int j0 = blockIdx.y * 128;
    const int h  = blockIdx.z;
    const int t  = threadIdx.x;

    #pragma unroll
    for (int r = 0; r < 2; r++) {
        int idx = t + 256 * r;
        int i = idx >> 4, d4 = (idx & 15) * 4;
        float4 v = *(const float4*)(g_q + (size_t)h * (Nn * Dn) + (size_t)(i0 + i) * Dn + d4);
        sQT[d4 + 0][i] = v.x; sQT[d4 + 1][i] = v.y; sQT[d4 + 2][i] = v.z; sQT[d4 + 3][i] = v.w;
    }
    #pragma unroll
    for (int r = 0; r < 8; r++) {
        int idx = t + 256 * r;
        int j = idx >> 4, d4 = (idx & 15) * 4;
        float4 v = *(const float4*)(kmat + (size_t)h * (Nn * Dn) + (size_t)(j0 + j) * Dn + d4);
        sKT[d4 + 0][j] = v.x; sKT[d4 + 1][j] = v.y; sKT[d4 + 2][j] = v.z; sKT[d4 + 3][j] = v.w;
    }
    __syncthreads();

    const int ii0 = (t >> 5) * 4;
    const int jj0 = (t & 31) * 4;
    float acc[4][4];
    #pragma unroll
    for (int u = 0; u < 4; u++)
        #pragma unroll
        for (int v = 0; v < 4; v++) acc[u][v] = 0.f;

    #pragma unroll 4
    for (int d = 0; d < 64; d++) {
        float4 rq = *(const float4*)&sQT[d][ii0];
        float4 rk = *(const float4*)&sKT[d][jj0];
        acc[0][0] += rq.x * rk.x; acc[0][1] += rq.x * rk.y; acc[0][2] += rq.x * rk.z; acc[0][3] += rq.x * rk.w;
        acc[1][0] += rq.y * rk.x; acc[1][1] += rq.y * rk.y; acc[1][2] += rq.y * rk.z; acc[1][3] += rq.y * rk.w;
        acc[2][0] += rq.z * rk.x; acc[2][1] += rq.z * rk.y; acc[2][2] += rq.z * rk.z; acc[2][3] += rq.z * rk.w;
        acc[3][0] += rq.w * rk.x; acc[3][1] += rq.w * rk.y; acc[3][2] += rq.w * rk.z; acc[3][3] += rq.w * rk.w;
    }

    #pragma unroll
    for (int u = 0; u < 4; u++) {
        float qbe = g_qbe[h * Nn + i0 + ii0 + u];
        float4 o = make_float4(acc[u][0] + qbe, acc[u][1] + qbe, acc[u][2] + qbe, acc[u][3] + qbe);
        *(float4*)(g_sim + ((size_t)(h * Nn + i0 + ii0 + u)) * Nn + j0 + jj0) = o;
    }
}

// ---------------- kernel 4: sim += qe . edges (per-node block; edges read once) --------
// grid 512 (one per i), 256 threads
__global__ void __launch_bounds__(256)
edgesim_kernel(const float* __restrict__ edges)
{
    __shared__ float sE[64][68];
    __shared__ float sQE[8][64];

    const int i = blockIdx.x;
    const int t = threadIdx.x;

    if (t < 128) {
        int h = t >> 4, c4 = (t & 15) * 4;
        *(float4*)&sQE[h][c4] = *(const float4*)(g_qe + (size_t)h * (Nn * DEn) + (size_t)i * DEn + c4);
    }

    const int j  = t & 63;
    const int hp = t >> 6;
    const int h0 = hp * 2, h1 = hp * 2 + 1;

    for (int jc = 0; jc < 8; jc++) {
        const int j0 = jc * 64;
        #pragma unroll
        for (int r = 0; r < 4; r++) {
            int idx = t + 256 * r;
            int jj = idx >> 4, c4 = (idx & 15) * 4;
            *(float4*)&sE[jj][c4] = *(const float4*)(edges + ((size_t)i * Nn + j0 + jj) * DEn + c4);
        }
        __syncthreads();

        const ulonglong2* ep   = (const ulonglong2*)&sE[j][0];
        const ulonglong2* qep0 = (const ulonglong2*)&sQE[h0][0];
        const ulonglong2* qep1 = (const ulonglong2*)&sQE[h1][0];
        ull a00 = 0, a01 = 0, a10 = 0, a11 = 0;
        #pragma unroll
        for (int q = 0; q < 16; q++) {
            ulonglong2 e  = ep[q];
            ulonglong2 q0 = qep0[q];
            ulonglong2 q1 = qep1[q];
            fma2(a00, q0.x, e.x); fma2(a01, q0.y, e.y);
            fma2(a10, q1.x, e.x); fma2(a11, q1.y, e.y);
        }
        float2 f00 = upk2(a00), f01 = upk2(a01), f10 = upk2(a10), f11 = upk2(a11);
        float s0 = f00.x + f00.y + f01.x + f01.y;
        float s1 = f10.x + f10.y + f11.x + f11.y;
        g_sim[((size_t)(h0 * Nn + i)) * Nn + j0 + j] += s0;
        g_sim[((size_t)(h1 * Nn + i)) * Nn + j0 + j] += s1;
        __syncthreads();
    }
}

// ---------------- kernel 5: row softmax (unnormalized p + 1/sum) ----------------
__global__ void __launch_bounds__(256)
softmax_kernel()
{
    const int t = threadIdx.x, w = t >> 5, l = t & 31;
    const int row = blockIdx.x * 8 + w;
    float* rp = g_sim + (size_t)row * Nn;

    float vals[16];
    float mx = -1e30f;
    #pragma unroll
    for (int jc = 0; jc < 16; jc++) {
        vals[jc] = rp[jc * 32 + l];
        mx = fmaxf(mx, vals[jc]);
    }
    #pragma unroll
    for (int off = 16; off > 0; off >>= 1) mx = fmaxf(mx, __shfl_xor_sync(0xffffffffu, mx, off));
    float s = 0.f;
    #pragma unroll
    for (int jc = 0; jc < 16; jc++) {
        float e = __expf(vals[jc] - mx);
        s += e;
        rp[jc * 32 + l] = e;
    }
    #pragma unroll
    for (int off = 16; off > 0; off >>= 1) s += __shfl_xor_sync(0xffffffffu, s, off);
    if (l == 0) g_sinv[row] = 1.0f / s;
}

// ---------------- kernel 6: att = (p @ v) * sinv ----------------
// grid (16 itiles, 8 heads), 256 threads
__global__ void __launch_bounds__(256)
pv_kernel(const float* __restrict__ vmat)
{
    __shared__ float sPT[64][36];   // [j][i] transposed chunk
    __shared__ float sV [64][68];   // [j][d]

    const int i0 = blockIdx.x * 32;
    const int h  = blockIdx.y;
    const int t  = threadIdx.x;
    const int i0t = (t >> 4) * 2;
    const int d0  = (t & 15) * 4;

    float acc[2][4];
    #pragma unroll
    for (int u = 0; u < 2; u++)
        #pragma unroll
        for (int v = 0; v < 4; v++) acc[u][v] = 0.f;

    for (int jc = 0; jc < 8; jc++) {
        const int j0 = jc * 64;
        #pragma unroll
        for (int r = 0; r < 2; r++) {
            int idx = t + 256 * r;
            int ii = idx >> 4, jj4 = (idx & 15) * 4;
            float4 v = *(const float4*)(g_sim + ((size_t)(h * Nn + i0 + ii)) * Nn + j0 + jj4);
            sPT[jj4 + 0][ii] = v.x; sPT[jj4 + 1][ii] = v.y; sPT[jj4 + 2][ii] = v.z; sPT[jj4 + 3][ii] = v.w;
        }
        #pragma unroll
        for (int r = 0; r < 4; r++) {
            int idx = t + 256 * r;
            int jj = idx >> 4, d4 = (idx & 15) * 4;
            *(float4*)&sV[jj][d4] = *(const float4*)(vmat + (size_t)h * (Nn * Dn) + (size_t)(j0 + jj) * Dn + d4);
        }
        __syncthreads();

        #pragma unroll 4
        for (int jj = 0; jj < 64; jj++) {
            float2 rp = *(const float2*)&sPT[jj][i0t];
            float4 rv = *(const float4*)&sV[jj][d0];
            acc[0][0] += rp.x * rv.x; acc[0][1] += rp.x * rv.y; acc[0][2] += rp.x * rv.z; acc[0][3] += rp.x * rv.w;
            acc[1][0] += rp.y * rv.x; acc[1][1] += rp.y * rv.y; acc[1][2] += rp.y * rv.z; acc[1][3] += rp.y * rv.w;
        }
        __syncthreads();
    }

    #pragma unroll
    for (int u = 0; u < 2; u++) {
        float s = g_sinv[h * Nn + i0 + i0t + u];
        float4 o = make_float4(acc[u][0] * s, acc[u][1] * s, acc[u][2] * s, acc[u][3] * s);
        *(float4*)(g_att + (size_t)h * (Nn * Dn) + (size_t)(i0 + i0t + u) * Dn + d0) = o;
    }
}

// ---------------- kernel 7: ew = (p @ edges) * sinv (per-node block) ----------------
// grid 512 (one per i), 256 threads
__global__ void __launch_bounds__(256)
ew_kernel(const float* __restrict__ edges)
{
    __shared__ float sP[8][512];    // 16 KB
    __shared__ float sE[32][68];

    const int i = blockIdx.x;
    const int t = threadIdx.x;

    #pragma unroll
    for (int r = 0; r < 4; r++) {
        int idx = t + 256 * r;
        int h = idx >> 7, j4 = (idx & 127) * 4;
        *(float4*)&sP[h][j4] = *(const float4*)(g_sim + ((size_t)(h * Nn + i)) * Nn + j4);
    }

    const int h  = t >> 5;
    const int c0 = (t & 31) * 2;
    ull acc = 0;

    for (int jc = 0; jc < 16; jc++) {
        const int j0 = jc * 32;
        #pragma unroll
        for (int r = 0; r < 2; r++) {
            int idx = t + 256 * r;
            int jj = idx >> 4, c4 = (idx & 15) * 4;
            *(float4*)&sE[jj][c4] = *(const float4*)(edges + ((size_t)i * Nn + j0 + jj) * DEn + c4);
        }
        __syncthreads();

        #pragma unroll 8
        for (int jj = 0; jj < 32; jj++) {
            ull e2 = *(const ull*)&sE[jj][c0];
            float pj = sP[h][j0 + jj];
            ull pd = pk2(pj, pj);
            fma2(acc, pd, e2);
        }
        __syncthreads();
    }

    float s = g_sinv[h * Nn + i];
    float2 f = upk2(acc);
    float2 o = make_float2(f.x * s, f.y * s);
    *(float2*)(g_ew + (size_t)h * (Nn * DEn) + (size_t)i * DEn + c0) = o;
}

// ---------------- kernel 8: out = [att|ew] @ [Wo;M] + bvec ----------------
// grid (64 itiles of 8, 2 col halves) = 128 blocks, 256 threads
__global__ void __launch_bounds__(256)
fuse_out_kernel(const float* __restrict__ Wo, float* __restrict__ out)
{
    __shared__ float sA[8][1024];   // 32 KB
    const int t = threadIdx.x;
    const int i0 = blockIdx.x * 8;
    const int colbase = blockIdx.y * 64;

    #pragma unroll
    for (int u = 0; u < 8; u++) {
        int idx = t + 256 * u;
        int r = idx >> 8, seg = idx & 255;
        float4 val;
        if (seg < 128) {
            int h = seg >> 4, d4 = (seg & 15) * 4;
            val = *(const float4*)(g_att + (size_t)h * (Nn * Dn) + (size_t)(i0 + r) * Dn + d4);
        } else {
            int s2 = seg - 128;
            int h = s2 >> 4, c4 = (s2 & 15) * 4;
            val = *(const float4*)(g_ew + (size_t)h * (Nn * DEn) + (size_t)(i0 + r) * DEn + c4);
        }
        *(float4*)(&sA[r][ (seg & 127) * 4 + (seg < 128 ? 0 : 512) ]) = val;
    }
    __syncthreads();

    const int col = (t & 63) + colbase;
    const int rh  = t >> 6;
    const int r0  = rh * 2;
    float acc0 = 0.f, acc1 = 0.f;

    #pragma unroll 8
    for (int k = 0; k < 512; k++) {
        float w = Wo[(size_t)k * DNn + col];
        acc0 += sA[r0][k] * w;
        acc1 += sA[r0 + 1][k] * w;
    }
    #pragma unroll 8
    for (int k = 0; k < 512; k++) {
        float w = g_M[(size_t)k * DNn + col];
        acc0 += sA[r0][512 + k] * w;
        acc1 += sA[r0 + 1][512 + k] * w;
    }

    float b = g_bvec[col];
    out[(size_t)(i0 + r0) * DNn + col]     = acc0 + b;
    out[(size_t)(i0 + r0 + 1) * DNn + col] = acc1 + b;
}

// ---------------- launch ----------------
extern "C" void kernel_launch(void* const* d_in, const int* in_sizes, int n_in,
                              void* d_out, int out_size)
{
    const float* nodes = (const float*)d_in[0];
    const float* edges = (const float*)d_in[1];
    const float* Wq = (const float*)d_in[3];
    const float* bq = (const float*)d_in[4];
    const float* Wk = (const float*)d_in[5];
    const float* bk = (const float*)d_in[6];
    const float* Wv = (const float*)d_in[7];
    const float* bv = (const float*)d_in[8];
    const float* We = (const float*)d_in[9];
    const float* be = (const float*)d_in[10];
    const float* Wo = (const float*)d_in[11];
    const float* bo = (const float*)d_in[12];
    float* out = (float*)d_out;

    float* kptr; float* vptr;
    cudaGetSymbolAddress((void**)&kptr, g_k);
    cudaGetSymbolAddress((void**)&vptr, g_v);

    dim3 g1(16, 24);
    qkv_kernel<<<g1, 256>>>(nodes, Wq, bq, Wk, bk, Wv, bv, We, be);
    wcomb_kernel<<<65, 256>>>(We, be, Wo, bo);
    qksim_kernel<<<dim3(16, 4, 8), 256>>>(kptr);
    edgesim_kernel<<<Nn, 256>>>(edges);
    softmax_kernel<<<Nn * Hn / 8, 256>>>();
    pv_kernel<<<dim3(16, 8), 256>>>(vptr);
    ew_kernel<<<Nn, 256>>>(edges);
    fuse_out_kernel<<<dim3(64, 2), 256>>>(Wo, out);
}